// round 1
// baseline (speedup 1.0000x reference)
#include <cuda_runtime.h>

// Problem constants
#define VDIM 256
#define VSLICE (256L * 256L * 256L)   // 16,777,216 voxels per output slice

// ---------------------------------------------------------------------------
// Zero-init kernel: d_out is poisoned to 0xAA, we need zeros before splatting.
// ---------------------------------------------------------------------------
__global__ void zero_kernel(float4* __restrict__ out, int n4) {
    int i = blockIdx.x * blockDim.x + threadIdx.x;
    if (i < n4) out[i] = make_float4(0.f, 0.f, 0.f, 0.f);
}

// ---------------------------------------------------------------------------
// Trilinear splat with scatter atomics (RED.add, no return).
// pts:  [total, 3] xyz in [-1, 1]   feat: [total]
// out:  one 256^3 fp32 volume (layout: z outermost, x innermost)
// scale folds the per-view-group mean (0.5 for the 2-view group, 1.0 for 1).
// ---------------------------------------------------------------------------
__global__ void splat_kernel(const float* __restrict__ pts,
                             const float* __restrict__ feat,
                             float* __restrict__ out,
                             float scale, int total) {
    int i = blockIdx.x * blockDim.x + threadIdx.x;
    if (i >= total) return;

    long base3 = 3L * (long)i;
    float x = pts[base3 + 0];
    float y = pts[base3 + 1];
    float z = pts[base3 + 2];
    float f = feat[i] * scale;

    // align_corners=True mapping: voxel = (p + 1) * (V-1)/2
    float fx = (x + 1.0f) * 127.5f;
    float fy = (y + 1.0f) * 127.5f;
    float fz = (z + 1.0f) * 127.5f;

    float lx = floorf(fx), ly = floorf(fy), lz = floorf(fz);
    int ix = (int)lx, iy = (int)ly, iz = (int)lz;
    float tx = fx - lx, ty = fy - ly, tz = fz - lz;

    // Fast path: all 8 corners guaranteed in range (lo in [0,254]).
    if ((unsigned)ix < 255u && (unsigned)iy < 255u && (unsigned)iz < 255u) {
        float* b = out + (((long)iz * VDIM + iy) * VDIM + ix);
        float ax = 1.0f - tx;
        float w00 = (1.0f - ty) * (1.0f - tz) * f;   // dy=0, dz=0
        float w10 = ty * (1.0f - tz) * f;            // dy=1, dz=0
        float w01 = (1.0f - ty) * tz * f;            // dy=0, dz=1
        float w11 = ty * tz * f;                     // dy=1, dz=1

        atomicAdd(b,                       w00 * ax);
        atomicAdd(b + 1,                   w00 * tx);
        atomicAdd(b + VDIM,                w10 * ax);
        atomicAdd(b + VDIM + 1,            w10 * tx);
        atomicAdd(b + VDIM * VDIM,         w01 * ax);
        atomicAdd(b + VDIM * VDIM + 1,     w01 * tx);
        atomicAdd(b + VDIM * VDIM + VDIM,     w11 * ax);
        atomicAdd(b + VDIM * VDIM + VDIM + 1, w11 * tx);
    } else {
        // Exact reference semantics for (never-expected) boundary points.
        #pragma unroll
        for (int dz = 0; dz < 2; dz++)
        #pragma unroll
        for (int dy = 0; dy < 2; dy++)
        #pragma unroll
        for (int dx = 0; dx < 2; dx++) {
            int jx = ix + dx, jy = iy + dy, jz = iz + dz;
            float w = (dx ? tx : 1.0f - tx) *
                      (dy ? ty : 1.0f - ty) *
                      (dz ? tz : 1.0f - tz) * f;
            if (jx >= 0 && jx < VDIM && jy >= 0 && jy < VDIM &&
                jz >= 0 && jz < VDIM) {
                atomicAdd(out + (((long)jz * VDIM + jy) * VDIM + jx), w);
            }
        }
    }
}

// ---------------------------------------------------------------------------
// kernel_launch
//   d_in[0]: points_3d  [3, P, 3] fp32   (in_sizes[0] = 3*P*3)
//   d_in[1]: points_features [3, P, 1] fp32 (in_sizes[1] = 3*P)
//   d_out:   [2, 1, 256, 256, 256] fp32
// Views 0,1 -> out slice 0 with scale 0.5 (mean of 2); view 2 -> slice 1.
// ---------------------------------------------------------------------------
extern "C" void kernel_launch(void* const* d_in, const int* in_sizes, int n_in,
                              void* d_out, int out_size) {
    const float* pts  = (const float*)d_in[0];
    const float* feat = (const float*)d_in[1];
    float* out = (float*)d_out;

    int BP = in_sizes[1];      // 3 * P
    int P  = BP / 3;           // points per view

    // Zero both output slices (out_size = 2 * 256^3 floats).
    int n4 = out_size / 4;
    zero_kernel<<<(n4 + 255) / 256, 256>>>((float4*)out, n4);

    // Views 0 and 1 -> slice 0, scaled by 0.5 (mean over the 2-view group).
    int totalA = 2 * P;
    splat_kernel<<<(totalA + 255) / 256, 256>>>(pts, feat, out, 0.5f, totalA);

    // View 2 -> slice 1, scale 1.0.
    splat_kernel<<<(P + 255) / 256, 256>>>(pts + 3L * (long)(2 * P),
                                           feat + 2L * (long)P,
                                           out + VSLICE, 1.0f, P);
}

// round 2
// speedup vs baseline: 1.0735x; 1.0735x over previous
#include <cuda_runtime.h>

#define VDIM 256
#define VSLICE (256L * 256L * 256L)

// ---------------------------------------------------------------------------
// Zero-init: 64B per thread.
// ---------------------------------------------------------------------------
__global__ void zero_kernel(float4* __restrict__ out, int n4) {
    int i = (blockIdx.x * blockDim.x + threadIdx.x) * 4;
    if (i + 3 < n4) {
        float4 z = make_float4(0.f, 0.f, 0.f, 0.f);
        out[i] = z; out[i + 1] = z; out[i + 2] = z; out[i + 3] = z;
    } else {
        for (int k = i; k < n4; k++) out[k] = make_float4(0.f, 0.f, 0.f, 0.f);
    }
}

// ---------------------------------------------------------------------------
// One vectorized reduction: adds {a,b,c,d} to 16B-aligned addr (no return).
// ---------------------------------------------------------------------------
__device__ __forceinline__ void red_v4(float* addr, float a, float b, float c, float d) {
    asm volatile("red.global.add.v4.f32 [%0], {%1, %2, %3, %4};"
                 :: "l"(addr), "f"(a), "f"(b), "f"(c), "f"(d)
                 : "memory");
}

// ---------------------------------------------------------------------------
// Splat one point. Fast path uses red.v4 covering the (ix, ix+1) pair inside
// its 16B-aligned quad; zero lanes are exact no-ops. ix%4==3 needs one extra
// scalar atomic for the straddling ix+1 element.
// ---------------------------------------------------------------------------
__device__ __forceinline__ void splat_one(float x, float y, float z, float f,
                                          float* __restrict__ out) {
    float fx = (x + 1.0f) * 127.5f;
    float fy = (y + 1.0f) * 127.5f;
    float fz = (z + 1.0f) * 127.5f;

    float lx = floorf(fx), ly = floorf(fy), lz = floorf(fz);
    int ix = (int)lx, iy = (int)ly, iz = (int)lz;
    float tx = fx - lx, ty = fy - ly, tz = fz - lz;

    if ((unsigned)ix < 255u && (unsigned)iy < 255u && (unsigned)iz < 255u) {
        int off = ix & 3;
        int ixa = ix & ~3;
        float* b0 = out + (((long)iz * VDIM + iy) * VDIM + ixa);

        float ax = 1.0f - tx;
        float w00 = (1.0f - ty) * (1.0f - tz) * f;
        float w10 = ty * (1.0f - tz) * f;
        float w01 = (1.0f - ty) * tz * f;
        float w11 = ty * tz * f;

        bool straddle = (off == 3);

        #pragma unroll
        for (int c = 0; c < 4; c++) {
            float w = (c == 0) ? w00 : (c == 1) ? w10 : (c == 2) ? w01 : w11;
            float wa = w * ax;         // goes to ix
            float wb = w * tx;         // goes to ix+1
            long rowoff = (c & 2) ? (long)VDIM * VDIM : 0L;
            if (c & 1) rowoff += VDIM;

            float v0 = (off == 0) ? wa : 0.0f;
            float v1 = (off == 0) ? wb : (off == 1) ? wa : 0.0f;
            float v2 = (off == 1) ? wb : (off == 2) ? wa : 0.0f;
            float v3 = (off == 2) ? wb : (off == 3) ? wa : 0.0f;

            red_v4(b0 + rowoff, v0, v1, v2, v3);
            if (straddle) atomicAdd(b0 + rowoff + 4, wb);
        }
    } else {
        // Exact reference semantics for boundary / out-of-range points.
        #pragma unroll
        for (int dz = 0; dz < 2; dz++)
        #pragma unroll
        for (int dy = 0; dy < 2; dy++)
        #pragma unroll
        for (int dx = 0; dx < 2; dx++) {
            int jx = ix + dx, jy = iy + dy, jz = iz + dz;
            float w = (dx ? tx : 1.0f - tx) *
                      (dy ? ty : 1.0f - ty) *
                      (dz ? tz : 1.0f - tz) * f;
            if (jx >= 0 && jx < VDIM && jy >= 0 && jy < VDIM &&
                jz >= 0 && jz < VDIM) {
                atomicAdd(out + (((long)jz * VDIM + jy) * VDIM + jx), w);
            }
        }
    }
}

// ---------------------------------------------------------------------------
// 4 points per thread with float4 loads (total must be a multiple of 4, which
// holds here; a scalar tail guard keeps it correct regardless).
// ---------------------------------------------------------------------------
__global__ void splat_kernel(const float4* __restrict__ pts4,
                             const float4* __restrict__ feat4,
                             const float* __restrict__ pts,
                             const float* __restrict__ feat,
                             float* __restrict__ out,
                             float scale, int total) {
    int t = blockIdx.x * blockDim.x + threadIdx.x;
    int p0 = t * 4;
    if (p0 >= total) return;

    if (p0 + 3 < total) {
        float4 a = pts4[3L * t];
        float4 b = pts4[3L * t + 1];
        float4 c = pts4[3L * t + 2];
        float4 ff = feat4[t];
        splat_one(a.x, a.y, a.z, ff.x * scale, out);
        splat_one(a.w, b.x, b.y, ff.y * scale, out);
        splat_one(b.z, b.w, c.x, ff.z * scale, out);
        splat_one(c.y, c.z, c.w, ff.w * scale, out);
    } else {
        for (int p = p0; p < total; p++) {
            splat_one(pts[3L * p], pts[3L * p + 1], pts[3L * p + 2],
                      feat[p] * scale, out);
        }
    }
}

// ---------------------------------------------------------------------------
// kernel_launch
// ---------------------------------------------------------------------------
extern "C" void kernel_launch(void* const* d_in, const int* in_sizes, int n_in,
                              void* d_out, int out_size) {
    const float* pts  = (const float*)d_in[0];
    const float* feat = (const float*)d_in[1];
    float* out = (float*)d_out;

    int BP = in_sizes[1];   // 3 * P
    int P  = BP / 3;

    int n4 = out_size / 4;                  // number of float4s
    int zthreads = (n4 + 3) / 4;
    zero_kernel<<<(zthreads + 255) / 256, 256>>>((float4*)out, n4);

    // Views 0,1 -> slice 0 (scale 0.5 folds the 2-view mean).
    int totalA = 2 * P;
    int tA = (totalA + 3) / 4;
    splat_kernel<<<(tA + 255) / 256, 256>>>((const float4*)pts,
                                            (const float4*)feat,
                                            pts, feat, out, 0.5f, totalA);

    // View 2 -> slice 1.
    const float* ptsB  = pts + 3L * (long)(2 * P);
    const float* featB = feat + 2L * (long)P;
    int tB = (P + 3) / 4;
    splat_kernel<<<(tB + 255) / 256, 256>>>((const float4*)ptsB,
                                            (const float4*)featB,
                                            ptsB, featB, out + VSLICE, 1.0f, P);
}

// round 3
// speedup vs baseline: 1.3562x; 1.2634x over previous
#include <cuda_runtime.h>

#define VDIM 256
#define VSLICE (256L * 256L * 256L)

// ---------------------------------------------------------------------------
// Zero-init: one coalesced float4 per thread (R1 version: 6.4 TB/s).
// ---------------------------------------------------------------------------
__global__ void zero_kernel(float4* __restrict__ out, int n4) {
    int i = blockIdx.x * blockDim.x + threadIdx.x;
    if (i < n4) out[i] = make_float4(0.f, 0.f, 0.f, 0.f);
}

__device__ __forceinline__ void red_v4(float* addr, float a, float b, float c, float d) {
    asm volatile("red.global.add.v4.f32 [%0], {%1, %2, %3, %4};"
                 :: "l"(addr), "f"(a), "f"(b), "f"(c), "f"(d)
                 : "memory");
}
__device__ __forceinline__ void red_v2(float* addr, float a, float b) {
    asm volatile("red.global.add.v2.f32 [%0], {%1, %2};"
                 :: "l"(addr), "f"(a), "f"(b)
                 : "memory");
}

// ---------------------------------------------------------------------------
// Splat one point: per corner-row, pick the cheapest RED encoding for the
// (ix, ix+1) pair based on ix alignment.
// ---------------------------------------------------------------------------
__device__ __forceinline__ void splat_one(float x, float y, float z, float f,
                                          float* __restrict__ out) {
    float fx = (x + 1.0f) * 127.5f;
    float fy = (y + 1.0f) * 127.5f;
    float fz = (z + 1.0f) * 127.5f;

    float lx = floorf(fx), ly = floorf(fy), lz = floorf(fz);
    int ix = (int)lx, iy = (int)ly, iz = (int)lz;
    float tx = fx - lx, ty = fy - ly, tz = fz - lz;

    if ((unsigned)ix < 255u && (unsigned)iy < 255u && (unsigned)iz < 255u) {
        float ax = 1.0f - tx;
        float w[4];
        w[0] = (1.0f - ty) * (1.0f - tz) * f;   // (iy,   iz)
        w[1] = ty * (1.0f - tz) * f;            // (iy+1, iz)
        w[2] = (1.0f - ty) * tz * f;            // (iy,   iz+1)
        w[3] = ty * tz * f;                     // (iy+1, iz+1)
        const long roff[4] = {0L, VDIM, (long)VDIM * VDIM, (long)VDIM * VDIM + VDIM};

        float* rowbase = out + (((long)iz * VDIM + iy) * VDIM);
        int off = ix & 3;

        if ((ix & 1) == 0) {
            // 8B-aligned pair: one v2 per row.
            #pragma unroll
            for (int c = 0; c < 4; c++)
                red_v2(rowbase + roff[c] + ix, w[c] * ax, w[c] * tx);
        } else if (off != 3) {
            // off == 1: pair in lanes {1,2} of the 16B quad.
            int ixa = ix & ~3;
            #pragma unroll
            for (int c = 0; c < 4; c++)
                red_v4(rowbase + roff[c] + ixa, 0.0f, w[c] * ax, w[c] * tx, 0.0f);
        } else {
            // off == 3: pair straddles the quad -> two scalars.
            #pragma unroll
            for (int c = 0; c < 4; c++) {
                atomicAdd(rowbase + roff[c] + ix,     w[c] * ax);
                atomicAdd(rowbase + roff[c] + ix + 1, w[c] * tx);
            }
        }
    } else {
        // Exact reference semantics for boundary / out-of-range points.
        #pragma unroll
        for (int dz = 0; dz < 2; dz++)
        #pragma unroll
        for (int dy = 0; dy < 2; dy++)
        #pragma unroll
        for (int dx = 0; dx < 2; dx++) {
            int jx = ix + dx, jy = iy + dy, jz = iz + dz;
            float wq = (dx ? tx : 1.0f - tx) *
                       (dy ? ty : 1.0f - ty) *
                       (dz ? tz : 1.0f - tz) * f;
            if (jx >= 0 && jx < VDIM && jy >= 0 && jy < VDIM &&
                jz >= 0 && jz < VDIM) {
                atomicAdd(out + (((long)jz * VDIM + jy) * VDIM + jx), wq);
            }
        }
    }
}

// ---------------------------------------------------------------------------
// Single merged splat: 4 points/thread with float4 loads. Point groups are
// 4-aligned and the 2P view boundary is a multiple of 4, so each group maps
// to exactly one output slice.
//   p < 2P  -> slice 0, scale 0.5 (mean of 2 views)
//   p >= 2P -> slice 1, scale 1.0
// ---------------------------------------------------------------------------
__global__ void splat_kernel(const float4* __restrict__ pts4,
                             const float4* __restrict__ feat4,
                             float* __restrict__ out,
                             int twoP, int total) {
    int t = blockIdx.x * blockDim.x + threadIdx.x;
    int p0 = t * 4;
    if (p0 >= total) return;

    float scale;
    float* dst;
    if (p0 < twoP) { scale = 0.5f; dst = out; }
    else           { scale = 1.0f; dst = out + VSLICE; }

    if (p0 + 3 < total) {
        float4 a  = pts4[3L * t];
        float4 b  = pts4[3L * t + 1];
        float4 c  = pts4[3L * t + 2];
        float4 ff = feat4[t];
        splat_one(a.x, a.y, a.z, ff.x * scale, dst);
        splat_one(a.w, b.x, b.y, ff.y * scale, dst);
        splat_one(b.z, b.w, c.x, ff.z * scale, dst);
        splat_one(c.y, c.z, c.w, ff.w * scale, dst);
    } else {
        const float* pts  = (const float*)pts4;
        const float* feat = (const float*)feat4;
        for (int p = p0; p < total; p++) {
            splat_one(pts[3L * p], pts[3L * p + 1], pts[3L * p + 2],
                      feat[p] * scale, dst);
        }
    }
}

// ---------------------------------------------------------------------------
// kernel_launch
// ---------------------------------------------------------------------------
extern "C" void kernel_launch(void* const* d_in, const int* in_sizes, int n_in,
                              void* d_out, int out_size) {
    const float* pts  = (const float*)d_in[0];
    const float* feat = (const float*)d_in[1];
    float* out = (float*)d_out;

    int BP = in_sizes[1];   // 3 * P
    int P  = BP / 3;

    int n4 = out_size / 4;
    zero_kernel<<<(n4 + 255) / 256, 256>>>((float4*)out, n4);

    int total = 3 * P;
    int threads = (total + 3) / 4;
    splat_kernel<<<(threads + 255) / 256, 256>>>((const float4*)pts,
                                                 (const float4*)feat,
                                                 out, 2 * P, total);
}

// round 5
// speedup vs baseline: 1.6106x; 1.1876x over previous
#include <cuda_runtime.h>

#define VDIM 256
#define VSLICE (256L * 256L * 256L)

// ---------------------------------------------------------------------------
// Zero-init: one coalesced float4 per thread.
// ---------------------------------------------------------------------------
__global__ void zero_kernel(float4* __restrict__ out, int n4) {
    int i = blockIdx.x * blockDim.x + threadIdx.x;
    if (i < n4) out[i] = make_float4(0.f, 0.f, 0.f, 0.f);
}

__device__ __forceinline__ void red_v4(float* addr, float a, float b, float c, float d) {
    asm volatile("red.global.add.v4.f32 [%0], {%1, %2, %3, %4};"
                 :: "l"(addr), "f"(a), "f"(b), "f"(c), "f"(d)
                 : "memory");
}
__device__ __forceinline__ void red_v2(float* addr, float a, float b) {
    asm volatile("red.global.add.v2.f32 [%0], {%1, %2};"
                 :: "l"(addr), "f"(a), "f"(b)
                 : "memory");
}

// ---------------------------------------------------------------------------
// Splat one point: per corner-row, cheapest RED encoding for the (ix, ix+1)
// pair given ix alignment.
// ---------------------------------------------------------------------------
__device__ __forceinline__ void splat_one(float x, float y, float z, float f,
                                          float* __restrict__ out) {
    float fx = (x + 1.0f) * 127.5f;
    float fy = (y + 1.0f) * 127.5f;
    float fz = (z + 1.0f) * 127.5f;

    float lx = floorf(fx), ly = floorf(fy), lz = floorf(fz);
    int ix = (int)lx, iy = (int)ly, iz = (int)lz;
    float tx = fx - lx, ty = fy - ly, tz = fz - lz;

    if ((unsigned)ix < 255u && (unsigned)iy < 255u && (unsigned)iz < 255u) {
        float ax = 1.0f - tx;
        float w[4];
        w[0] = (1.0f - ty) * (1.0f - tz) * f;   // (iy,   iz)
        w[1] = ty * (1.0f - tz) * f;            // (iy+1, iz)
        w[2] = (1.0f - ty) * tz * f;            // (iy,   iz+1)
        w[3] = ty * tz * f;                     // (iy+1, iz+1)
        const long roff[4] = {0L, VDIM, (long)VDIM * VDIM, (long)VDIM * VDIM + VDIM};

        float* rowbase = out + (((long)iz * VDIM + iy) * VDIM);
        int off = ix & 3;

        if ((ix & 1) == 0) {
            #pragma unroll
            for (int c = 0; c < 4; c++)
                red_v2(rowbase + roff[c] + ix, w[c] * ax, w[c] * tx);
        } else if (off != 3) {
            int ixa = ix & ~3;
            #pragma unroll
            for (int c = 0; c < 4; c++)
                red_v4(rowbase + roff[c] + ixa, 0.0f, w[c] * ax, w[c] * tx, 0.0f);
        } else {
            #pragma unroll
            for (int c = 0; c < 4; c++) {
                atomicAdd(rowbase + roff[c] + ix,     w[c] * ax);
                atomicAdd(rowbase + roff[c] + ix + 1, w[c] * tx);
            }
        }
    } else {
        // Exact reference semantics for boundary / out-of-range points.
        #pragma unroll
        for (int dz = 0; dz < 2; dz++)
        #pragma unroll
        for (int dy = 0; dy < 2; dy++)
        #pragma unroll
        for (int dx = 0; dx < 2; dx++) {
            int jx = ix + dx, jy = iy + dy, jz = iz + dz;
            float wq = (dx ? tx : 1.0f - tx) *
                       (dy ? ty : 1.0f - ty) *
                       (dz ? tz : 1.0f - tz) * f;
            if (jx >= 0 && jx < VDIM && jy >= 0 && jy < VDIM &&
                jz >= 0 && jz < VDIM) {
                atomicAdd(out + (((long)jz * VDIM + jy) * VDIM + jx), wq);
            }
        }
    }
}

// ---------------------------------------------------------------------------
// Per-phase splat: 4 points/thread, float4 loads, single output slice.
// ---------------------------------------------------------------------------
__global__ void splat_kernel(const float4* __restrict__ pts4,
                             const float4* __restrict__ feat4,
                             float* __restrict__ out,
                             float scale, int total) {
    int t = blockIdx.x * blockDim.x + threadIdx.x;
    int p0 = t * 4;
    if (p0 >= total) return;

    if (p0 + 3 < total) {
        float4 a  = pts4[3L * t];
        float4 b  = pts4[3L * t + 1];
        float4 c  = pts4[3L * t + 2];
        float4 ff = feat4[t];
        splat_one(a.x, a.y, a.z, ff.x * scale, out);
        splat_one(a.w, b.x, b.y, ff.y * scale, out);
        splat_one(b.z, b.w, c.x, ff.z * scale, out);
        splat_one(c.y, c.z, c.w, ff.w * scale, out);
    } else {
        const float* pts  = (const float*)pts4;
        const float* feat = (const float*)feat4;
        for (int p = p0; p < total; p++) {
            splat_one(pts[3L * p], pts[3L * p + 1], pts[3L * p + 2],
                      feat[p] * scale, out);
        }
    }
}

// ---------------------------------------------------------------------------
// kernel_launch: zero0 -> splat(views 0,1 -> slice0) -> zero1 -> splat(view 2
// -> slice1). Sequential phases keep each 64 MB atomic working set L2-resident.
// ---------------------------------------------------------------------------
extern "C" void kernel_launch(void* const* d_in, const int* in_sizes, int n_in,
                              void* d_out, int out_size) {
    const float* pts  = (const float*)d_in[0];
    const float* feat = (const float*)d_in[1];
    float* out = (float*)d_out;

    int BP = in_sizes[1];   // 3 * P
    int P  = BP / 3;

    int half4 = (int)(VSLICE / 4);   // float4s per slice

    // Phase A: slice 0 (views 0,1; scale 0.5 folds the 2-view mean).
    zero_kernel<<<(half4 + 255) / 256, 256>>>((float4*)out, half4);
    int totalA = 2 * P;
    int tA = (totalA + 3) / 4;
    splat_kernel<<<(tA + 255) / 256, 256>>>((const float4*)pts,
                                            (const float4*)feat,
                                            out, 0.5f, totalA);

    // Phase B: slice 1 (view 2).
    float* out1 = out + VSLICE;
    zero_kernel<<<(half4 + 255) / 256, 256>>>((float4*)out1, half4);
    const float* ptsB  = pts + 3L * (long)(2 * P);
    const float* featB = feat + 2L * (long)P;
    int tB = (P + 3) / 4;
    splat_kernel<<<(tB + 255) / 256, 256>>>((const float4*)ptsB,
                                            (const float4*)featB,
                                            out1, 1.0f, P);
}